// round 6
// baseline (speedup 1.0000x reference)
#include <cuda_runtime.h>
#include <cstdint>

// UWNeRF RGB renderer: R=65536 rays, S=128 samples.
// Persistent warp-per-ray kernel with cp.async double-buffered prefetch.
//  - 444 CTAs (148 SMs x 3) x 128 threads: single wave, grid-stride over rays.
//  - Each warp prefetches its NEXT ray's 14x128B via cp.async (LDGSTS: no dest
//    register -> ptxas cannot sink the loads; MLP=14 by construction) into a
//    per-warp smem double buffer while computing the current ray from smem.
//  - Per-thread cp.async groups + each thread reads only its own data ->
//    no __syncthreads needed at all.
// Outputs: (rgb, restored, direct, backscatter), each [R,3], concatenated.

#define NUM_R 65536
#define NUM_S 128
#define CTAS  444
#define THREADS 128
#define WPC 4
#define TOTAL_WARPS (CTAS * WPC)      // 1776
#define SLOTS 14                       // float4 slots per lane per ray
#define SMEM_BYTES (2 * WPC * SLOTS * 32 * 16)  // 57344

__device__ __forceinline__ float clip01(float x) { return __saturatef(x); }

__device__ __forceinline__ uint32_t s2u(const void* p) {
    return (uint32_t)__cvta_generic_to_shared(p);
}
__device__ __forceinline__ void cpa16(uint32_t s, const void* g) {
    asm volatile("cp.async.cg.shared.global [%0], [%1], 16;" :: "r"(s), "l"(g));
}
#define CP_COMMIT() asm volatile("cp.async.commit_group;")
#define CP_WAIT(n)  asm volatile("cp.async.wait_group %0;" :: "n"(n))

// Exclusive prefix sum over 128 samples distributed 4-per-lane (contiguous).
__device__ __forceinline__ void warp_excl_scan4(const float v[4], float excl[4], int lane) {
    float p0 = v[0];
    float p1 = p0 + v[1];
    float p2 = p1 + v[2];
    float p3 = p2 + v[3];
    float x = p3;
    #pragma unroll
    for (int off = 1; off < 32; off <<= 1) {
        float y = __shfl_up_sync(0xffffffffu, x, off);
        x += (lane >= off) ? y : 0.0f;
    }
    float le = x - p3;
    excl[0] = le;
    excl[1] = le + p0;
    excl[2] = le + p1;
    excl[3] = le + p2;
}

// Issue the 14 cp.async (16B each) for ray `ray` into the warp buffer at `bu`.
// Slot layout: 0 deltas, 1 densities, 2-4 rgbs, 5-7 veiling, 8-10 direct, 11-13 backsc.
__device__ __forceinline__ void prefetch_ray(
    uint32_t bu, int ray, int lane,
    const float* densities, const float* rgbs, const float* veiling,
    const float* direct_coeffs, const float* backsc_coeffs, const float* deltas)
{
    const size_t sbase = (size_t)ray * NUM_S + (size_t)lane * 4;
    const size_t cbase = (size_t)ray * NUM_S * 3 + (size_t)lane * 12;
    cpa16(bu + (0 * 32 + lane) * 16, deltas + sbase);
    cpa16(bu + (1 * 32 + lane) * 16, densities + sbase);
    #pragma unroll
    for (int j = 0; j < 3; j++) {
        cpa16(bu + ((2  + j) * 32 + lane) * 16, rgbs          + cbase + j * 4);
        cpa16(bu + ((5  + j) * 32 + lane) * 16, veiling       + cbase + j * 4);
        cpa16(bu + ((8  + j) * 32 + lane) * 16, direct_coeffs + cbase + j * 4);
        cpa16(bu + ((11 + j) * 32 + lane) * 16, backsc_coeffs + cbase + j * 4);
    }
}

__global__ __launch_bounds__(THREADS)
void uwnerf_render_kernel(
    const float* __restrict__ densities,     // [R,S,1]
    const float* __restrict__ rgbs,          // [R,S,3]
    const float* __restrict__ veiling,       // [R,S,3]
    const float* __restrict__ direct_coeffs, // [R,S,3]
    const float* __restrict__ backsc_coeffs, // [R,S,3]
    const float* __restrict__ deltas,        // [R,S,1]
    float* __restrict__ out)                 // [4, R, 3]
{
    extern __shared__ float4 sm[];
    const int wid  = threadIdx.x >> 5;
    const int lane = threadIdx.x & 31;
    const int wgid = blockIdx.x * WPC + wid;

    // Per-warp double buffers (float4[SLOTS][32] each).
    float4* wb[2] = { sm + (size_t)wid * SLOTS * 32,
                      sm + (size_t)(WPC + wid) * SLOTS * 32 };
    const uint32_t wbu[2] = { s2u(wb[0]), s2u(wb[1]) };

    int ray = wgid;   // TOTAL_WARPS < NUM_R, so every warp has >= 1 ray
    prefetch_ray(wbu[0], ray, lane, densities, rgbs, veiling,
                 direct_coeffs, backsc_coeffs, deltas);
    CP_COMMIT();

    int b = 0;
    while (ray < NUM_R) {
        const int nray = ray + TOTAL_WARPS;
        if (nray < NUM_R) {
            prefetch_ray(wbu[b ^ 1], nray, lane, densities, rgbs, veiling,
                         direct_coeffs, backsc_coeffs, deltas);
            CP_COMMIT();
            CP_WAIT(1);   // current ray's group complete; next still in flight
        } else {
            CP_WAIT(0);
        }
        const float4* w4 = wb[b];

        // ---- pull this lane's data from smem (conflict-free LDS.128) ----
        float dlv[4], dev[4];
        *reinterpret_cast<float4*>(dlv) = w4[0 * 32 + lane];
        *reinterpret_cast<float4*>(dev) = w4[1 * 32 + lane];
        float rgbv[12], veilv[12];
        #pragma unroll
        for (int j = 0; j < 3; j++) {
            *reinterpret_cast<float4*>(&rgbv[j * 4])  = w4[(2 + j) * 32 + lane];
            *reinterpret_cast<float4*>(&veilv[j * 4]) = w4[(5 + j) * 32 + lane];
        }

        float dd[4];
        #pragma unroll
        for (int j = 0; j < 4; j++) dd[j] = dlv[j] * dev[j];

        // ---- object transmittance / weights ----
        float ex[4];
        warp_excl_scan4(dd, ex, lane);

        float w[4];
        float wsum = 0.0f;
        float rest[3] = {0.0f, 0.0f, 0.0f};
        #pragma unroll
        for (int j = 0; j < 4; j++) {
            float T     = __expf(-ex[j]);
            float alpha = 1.0f - __expf(-dd[j]);
            w[j] = alpha * T;
            wsum += w[j];
            rest[0] += w[j] * rgbv[j * 3 + 0];
            rest[1] += w[j] * rgbv[j * 3 + 1];
            rest[2] += w[j] * rgbv[j * 3 + 2];
        }

        // ---- direct attenuation: 3 scans over delta*direct_coeffs ----
        float dir[3] = {0.0f, 0.0f, 0.0f};
        {
            float dircv[12];
            #pragma unroll
            for (int j = 0; j < 3; j++)
                *reinterpret_cast<float4*>(&dircv[j * 4]) = w4[(8 + j) * 32 + lane];
            #pragma unroll
            for (int c = 0; c < 3; c++) {
                float v[4], e[4];
                #pragma unroll
                for (int j = 0; j < 4; j++) v[j] = dlv[j] * dircv[j * 3 + c];
                warp_excl_scan4(v, e, lane);
                #pragma unroll
                for (int j = 0; j < 4; j++)
                    dir[c] += w[j] * __expf(-e[j]) * rgbv[j * 3 + c];
            }
        }

        // ---- backscatter attenuation ----
        float obs[3] = {0.0f, 0.0f, 0.0f};
        {
            float bscv[12];
            #pragma unroll
            for (int j = 0; j < 3; j++)
                *reinterpret_cast<float4*>(&bscv[j * 4]) = w4[(11 + j) * 32 + lane];
            #pragma unroll
            for (int c = 0; c < 3; c++) {
                float v[4], e[4];
                #pragma unroll
                for (int j = 0; j < 4; j++) v[j] = dlv[j] * bscv[j * 3 + c];
                warp_excl_scan4(v, e, lane);
                #pragma unroll
                for (int j = 0; j < 4; j++)
                    obs[c] += w[j] * (1.0f - __expf(-e[j])) * veilv[j * 3 + c];
            }
        }

        // ---- warp reductions (10 accumulators) ----
        #pragma unroll
        for (int off = 16; off > 0; off >>= 1) {
            wsum += __shfl_down_sync(0xffffffffu, wsum, off);
            #pragma unroll
            for (int c = 0; c < 3; c++) {
                rest[c] += __shfl_down_sync(0xffffffffu, rest[c], off);
                dir[c]  += __shfl_down_sync(0xffffffffu, dir[c], off);
                obs[c]  += __shfl_down_sync(0xffffffffu, obs[c], off);
            }
        }

        // ---- lane 0 owns sample 0 (veiling_light[:,0,:]) and writes out ----
        if (lane == 0) {
            const float omask = clip01(wsum);
            const size_t RT3 = (size_t)NUM_R * 3;
            #pragma unroll
            for (int c = 0; c < 3; c++) {
                float medium = (1.0f - omask) * veilv[c];  // veiling at s=0
                float bs_ray = obs[c] + medium;
                out[0 * RT3 + (size_t)ray * 3 + c] = clip01(dir[c] + bs_ray);
                out[1 * RT3 + (size_t)ray * 3 + c] = clip01(rest[c]);
                out[2 * RT3 + (size_t)ray * 3 + c] = clip01(dir[c]);
                out[3 * RT3 + (size_t)ray * 3 + c] = clip01(bs_ray);
            }
        }

        b ^= 1;
        ray = nray;
    }
}

extern "C" void kernel_launch(void* const* d_in, const int* in_sizes, int n_in,
                              void* d_out, int out_size) {
    const float* densities     = (const float*)d_in[0];
    const float* rgbs          = (const float*)d_in[1];
    const float* veiling       = (const float*)d_in[2];
    const float* direct_coeffs = (const float*)d_in[3];
    const float* backsc_coeffs = (const float*)d_in[4];
    const float* deltas        = (const float*)d_in[5];
    float* out = (float*)d_out;

    // 57344 B dynamic smem > 48K default: opt in (idempotent, capture-safe).
    cudaFuncSetAttribute(uwnerf_render_kernel,
                         cudaFuncAttributeMaxDynamicSharedMemorySize, SMEM_BYTES);
    uwnerf_render_kernel<<<CTAS, THREADS, SMEM_BYTES>>>(
        densities, rgbs, veiling, direct_coeffs, backsc_coeffs, deltas, out);
}

// round 7
// speedup vs baseline: 1.2490x; 1.2490x over previous
#include <cuda_runtime.h>

// UWNeRF RGB renderer: R=65536 rays, S=128 samples.
// PERSISTENT warp-per-ray kernel: 1628 CTAs (148 SM x 11 = exact RF-limited
// residency at 46 regs) x 128 threads; each warp grid-strides over ~10 rays.
// Single wave -> no CTA churn (R2's achieved-occ gap: 56% vs 69% theoretical).
// Lane l owns contiguous samples [4l,4l+3] -> coalesced float4 LDG.E.128.
// R6 lesson: occupancy beats batched MLP here -> plain loads, max warps.
// Outputs: (rgb, restored, direct, backscatter), each [R,3], concatenated.

#define NUM_R 65536
#define NUM_S 128
#define CTAS  1628
#define THREADS 128
#define WPC 4
#define TOTAL_WARPS (CTAS * WPC)   // 6512

__device__ __forceinline__ float clip01(float x) { return __saturatef(x); }

// Exclusive prefix sum over 128 samples distributed 4-per-lane (contiguous).
__device__ __forceinline__ void warp_excl_scan4(const float v[4], float excl[4], int lane) {
    float p0 = v[0];
    float p1 = p0 + v[1];
    float p2 = p1 + v[2];
    float p3 = p2 + v[3];
    float x = p3;
    #pragma unroll
    for (int off = 1; off < 32; off <<= 1) {
        float y = __shfl_up_sync(0xffffffffu, x, off);
        x += (lane >= off) ? y : 0.0f;
    }
    float le = x - p3;  // exclusive prefix of this lane's 4-sample block
    excl[0] = le;
    excl[1] = le + p0;
    excl[2] = le + p1;
    excl[3] = le + p2;
}

__global__ __launch_bounds__(THREADS, 11)
void uwnerf_render_kernel(
    const float* __restrict__ densities,     // [R,S,1]
    const float* __restrict__ rgbs,          // [R,S,3]
    const float* __restrict__ veiling,       // [R,S,3]
    const float* __restrict__ direct_coeffs, // [R,S,3]
    const float* __restrict__ backsc_coeffs, // [R,S,3]
    const float* __restrict__ deltas,        // [R,S,1]
    float* __restrict__ out)                 // [4, R, 3]
{
    const int lane = threadIdx.x & 31;
    const int wgid = blockIdx.x * WPC + (threadIdx.x >> 5);

    // Warp-uniform ray loop: all lanes iterate together (shfls stay full-warp).
    for (int ray = wgid; ray < NUM_R; ray += TOTAL_WARPS) {
        const size_t sbase = (size_t)ray * NUM_S;
        const size_t cbase = sbase * 3 + (size_t)lane * 12;

        // ---- scalar arrays: lane loads 4 contiguous samples as one float4 --
        const float4 dl = reinterpret_cast<const float4*>(deltas    + sbase)[lane];
        const float4 de = reinterpret_cast<const float4*>(densities + sbase)[lane];
        const float dlt[4] = {dl.x, dl.y, dl.z, dl.w};
        float dd[4] = {dl.x * de.x, dl.y * de.y, dl.z * de.z, dl.w * de.w};

        float rgbv[12], veilv[12];
        {
            const float4* p = reinterpret_cast<const float4*>(rgbs + cbase);
            *reinterpret_cast<float4*>(&rgbv[0]) = p[0];
            *reinterpret_cast<float4*>(&rgbv[4]) = p[1];
            *reinterpret_cast<float4*>(&rgbv[8]) = p[2];
            p = reinterpret_cast<const float4*>(veiling + cbase);
            *reinterpret_cast<float4*>(&veilv[0]) = p[0];
            *reinterpret_cast<float4*>(&veilv[4]) = p[1];
            *reinterpret_cast<float4*>(&veilv[8]) = p[2];
        }

        // ---- object transmittance / weights ----
        float ex[4];
        warp_excl_scan4(dd, ex, lane);

        float w[4];
        float wsum = 0.0f;
        float rest[3] = {0.0f, 0.0f, 0.0f};
        #pragma unroll
        for (int j = 0; j < 4; j++) {
            float T     = __expf(-ex[j]);
            float alpha = 1.0f - __expf(-dd[j]);
            w[j] = alpha * T;
            wsum += w[j];
            rest[0] += w[j] * rgbv[j * 3 + 0];
            rest[1] += w[j] * rgbv[j * 3 + 1];
            rest[2] += w[j] * rgbv[j * 3 + 2];
        }

        // ---- direct attenuation: 3 scans over delta*direct_coeffs ----
        float dir[3] = {0.0f, 0.0f, 0.0f};
        {
            float dircv[12];
            const float4* p = reinterpret_cast<const float4*>(direct_coeffs + cbase);
            *reinterpret_cast<float4*>(&dircv[0]) = p[0];
            *reinterpret_cast<float4*>(&dircv[4]) = p[1];
            *reinterpret_cast<float4*>(&dircv[8]) = p[2];
            #pragma unroll
            for (int c = 0; c < 3; c++) {
                float v[4], e[4];
                #pragma unroll
                for (int j = 0; j < 4; j++) v[j] = dlt[j] * dircv[j * 3 + c];
                warp_excl_scan4(v, e, lane);
                #pragma unroll
                for (int j = 0; j < 4; j++)
                    dir[c] += w[j] * __expf(-e[j]) * rgbv[j * 3 + c];
            }
        }

        // ---- backscatter attenuation: 3 scans over delta*backscatter ----
        float obs[3] = {0.0f, 0.0f, 0.0f};
        {
            float bscv[12];
            const float4* p = reinterpret_cast<const float4*>(backsc_coeffs + cbase);
            *reinterpret_cast<float4*>(&bscv[0]) = p[0];
            *reinterpret_cast<float4*>(&bscv[4]) = p[1];
            *reinterpret_cast<float4*>(&bscv[8]) = p[2];
            #pragma unroll
            for (int c = 0; c < 3; c++) {
                float v[4], e[4];
                #pragma unroll
                for (int j = 0; j < 4; j++) v[j] = dlt[j] * bscv[j * 3 + c];
                warp_excl_scan4(v, e, lane);
                #pragma unroll
                for (int j = 0; j < 4; j++)
                    obs[c] += w[j] * (1.0f - __expf(-e[j])) * veilv[j * 3 + c];
            }
        }

        // ---- warp reductions (10 accumulators) ----
        #pragma unroll
        for (int off = 16; off > 0; off >>= 1) {
            wsum += __shfl_down_sync(0xffffffffu, wsum, off);
            #pragma unroll
            for (int c = 0; c < 3; c++) {
                rest[c] += __shfl_down_sync(0xffffffffu, rest[c], off);
                dir[c]  += __shfl_down_sync(0xffffffffu, dir[c], off);
                obs[c]  += __shfl_down_sync(0xffffffffu, obs[c], off);
            }
        }

        // ---- lane 0 owns sample 0 (veiling_light[:,0,:]) and writes out ----
        if (lane == 0) {
            const float omask = clip01(wsum);
            const size_t RT3 = (size_t)NUM_R * 3;
            #pragma unroll
            for (int c = 0; c < 3; c++) {
                float medium = (1.0f - omask) * veilv[c];  // veiling at s=0
                float bs_ray = obs[c] + medium;
                out[0 * RT3 + (size_t)ray * 3 + c] = clip01(dir[c] + bs_ray);
                out[1 * RT3 + (size_t)ray * 3 + c] = clip01(rest[c]);
                out[2 * RT3 + (size_t)ray * 3 + c] = clip01(dir[c]);
                out[3 * RT3 + (size_t)ray * 3 + c] = clip01(bs_ray);
            }
        }
    }
}

extern "C" void kernel_launch(void* const* d_in, const int* in_sizes, int n_in,
                              void* d_out, int out_size) {
    const float* densities     = (const float*)d_in[0];
    const float* rgbs          = (const float*)d_in[1];
    const float* veiling       = (const float*)d_in[2];
    const float* direct_coeffs = (const float*)d_in[3];
    const float* backsc_coeffs = (const float*)d_in[4];
    const float* deltas        = (const float*)d_in[5];
    float* out = (float*)d_out;

    uwnerf_render_kernel<<<CTAS, THREADS>>>(
        densities, rgbs, veiling, direct_coeffs, backsc_coeffs, deltas, out);
}

// round 8
// speedup vs baseline: 1.5557x; 1.2455x over previous
#include <cuda_runtime.h>

// UWNeRF RGB renderer: R=65536 rays, S=128 samples.
// Warp-per-ray, non-persistent (16384 CTAs x 128thr — the churn IS the
// pipeline: fresh CTAs issue load bursts continuously; R7 proved persistence
// hurts). This round: all 7 Kogge-Stone scans INTERLEAVED (independent shfl
// chains pipeline -> compute phase ~4x shorter -> warps return to load phase
// sooner). Object weights telescoped: w_j = E_j - E_{j+1} (5 exps not 8).
// Outputs: (rgb, restored, direct, backscatter), each [R,3], concatenated.

#define NUM_R 65536
#define NUM_S 128

__device__ __forceinline__ float clip01(float x) { return __saturatef(x); }

__global__ __launch_bounds__(128)
void uwnerf_render_kernel(
    const float* __restrict__ densities,     // [R,S,1]
    const float* __restrict__ rgbs,          // [R,S,3]
    const float* __restrict__ veiling,       // [R,S,3]
    const float* __restrict__ direct_coeffs, // [R,S,3]
    const float* __restrict__ backsc_coeffs, // [R,S,3]
    const float* __restrict__ deltas,        // [R,S,1]
    float* __restrict__ out)                 // [4, R, 3]
{
    const int r    = (blockIdx.x * blockDim.x + threadIdx.x) >> 5;
    const int lane = threadIdx.x & 31;

    const size_t sbase = (size_t)r * NUM_S;
    const size_t cbase = sbase * 3 + (size_t)lane * 12;

    // ---- loads: lane owns 4 contiguous samples -> coalesced LDG.E.128 ----
    const float4 dl = reinterpret_cast<const float4*>(deltas    + sbase)[lane];
    const float4 de = reinterpret_cast<const float4*>(densities + sbase)[lane];
    const float dlt[4] = {dl.x, dl.y, dl.z, dl.w};

    float rgbv[12], veilv[12];
    {
        const float4* p = reinterpret_cast<const float4*>(rgbs + cbase);
        *reinterpret_cast<float4*>(&rgbv[0]) = p[0];
        *reinterpret_cast<float4*>(&rgbv[4]) = p[1];
        *reinterpret_cast<float4*>(&rgbv[8]) = p[2];
        p = reinterpret_cast<const float4*>(veiling + cbase);
        *reinterpret_cast<float4*>(&veilv[0]) = p[0];
        *reinterpret_cast<float4*>(&veilv[4]) = p[1];
        *reinterpret_cast<float4*>(&veilv[8]) = p[2];
    }

    // ---- build local inclusive prefixes for 7 scan channels ----
    // ch 0: delta*density; ch 1-3: delta*direct[c]; ch 4-6: delta*backsc[c]
    float P[7][4];
    {
        P[0][0] = dlt[0] * de.x;
        P[0][1] = P[0][0] + dlt[1] * de.y;
        P[0][2] = P[0][1] + dlt[2] * de.z;
        P[0][3] = P[0][2] + dlt[3] * de.w;

        float dircv[12], bscv[12];
        const float4* p = reinterpret_cast<const float4*>(direct_coeffs + cbase);
        *reinterpret_cast<float4*>(&dircv[0]) = p[0];
        *reinterpret_cast<float4*>(&dircv[4]) = p[1];
        *reinterpret_cast<float4*>(&dircv[8]) = p[2];
        p = reinterpret_cast<const float4*>(backsc_coeffs + cbase);
        *reinterpret_cast<float4*>(&bscv[0]) = p[0];
        *reinterpret_cast<float4*>(&bscv[4]) = p[1];
        *reinterpret_cast<float4*>(&bscv[8]) = p[2];

        #pragma unroll
        for (int c = 0; c < 3; c++) {
            P[1 + c][0] = dlt[0] * dircv[0 * 3 + c];
            P[4 + c][0] = dlt[0] * bscv[0 * 3 + c];
            #pragma unroll
            for (int j = 1; j < 4; j++) {
                P[1 + c][j] = P[1 + c][j - 1] + dlt[j] * dircv[j * 3 + c];
                P[4 + c][j] = P[4 + c][j - 1] + dlt[j] * bscv[j * 3 + c];
            }
        }
    }

    // ---- 7 interleaved Kogge-Stone warp scans (independent shfl chains) ----
    float le[7];
    {
        float x[7];
        #pragma unroll
        for (int i = 0; i < 7; i++) x[i] = P[i][3];
        #pragma unroll
        for (int off = 1; off < 32; off <<= 1) {
            #pragma unroll
            for (int i = 0; i < 7; i++) {
                float y = __shfl_up_sync(0xffffffffu, x[i], off);
                x[i] += (lane >= off) ? y : 0.0f;
            }
        }
        #pragma unroll
        for (int i = 0; i < 7; i++) le[i] = x[i] - P[i][3];
    }

    // ---- object weights via telescoping: w_j = E_j - E_{j+1} ----
    float w[4];
    float wsum;
    float rest[3];
    {
        float E[5];
        E[0] = __expf(-le[0]);
        #pragma unroll
        for (int j = 0; j < 4; j++) E[j + 1] = __expf(-(le[0] + P[0][j]));
        #pragma unroll
        for (int j = 0; j < 4; j++) w[j] = E[j] - E[j + 1];
        wsum = E[0] - E[4];
        #pragma unroll
        for (int c = 0; c < 3; c++)
            rest[c] = w[0] * rgbv[c] + w[1] * rgbv[3 + c]
                    + w[2] * rgbv[6 + c] + w[3] * rgbv[9 + c];
    }

    // ---- direct & backscatter accumulation (12 + 12 exps, all independent) --
    float dir[3], obs[3];
    #pragma unroll
    for (int c = 0; c < 3; c++) {
        const float ld = le[1 + c];
        float A0 = __expf(-ld);
        float A1 = __expf(-(ld + P[1 + c][0]));
        float A2 = __expf(-(ld + P[1 + c][1]));
        float A3 = __expf(-(ld + P[1 + c][2]));
        dir[c] = w[0] * A0 * rgbv[c]     + w[1] * A1 * rgbv[3 + c]
               + w[2] * A2 * rgbv[6 + c] + w[3] * A3 * rgbv[9 + c];

        const float lb = le[4 + c];
        float B0 = __expf(-lb);
        float B1 = __expf(-(lb + P[4 + c][0]));
        float B2 = __expf(-(lb + P[4 + c][1]));
        float B3 = __expf(-(lb + P[4 + c][2]));
        obs[c] = w[0] * (1.0f - B0) * veilv[c]
               + w[1] * (1.0f - B1) * veilv[3 + c]
               + w[2] * (1.0f - B2) * veilv[6 + c]
               + w[3] * (1.0f - B3) * veilv[9 + c];
    }

    // ---- warp reductions (10 accumulators, chains interleaved) ----
    #pragma unroll
    for (int off = 16; off > 0; off >>= 1) {
        wsum += __shfl_down_sync(0xffffffffu, wsum, off);
        #pragma unroll
        for (int c = 0; c < 3; c++) {
            rest[c] += __shfl_down_sync(0xffffffffu, rest[c], off);
            dir[c]  += __shfl_down_sync(0xffffffffu, dir[c], off);
            obs[c]  += __shfl_down_sync(0xffffffffu, obs[c], off);
        }
    }

    // ---- lane 0 owns sample 0 (veiling_light[:,0,:]) and writes outputs ----
    if (lane == 0) {
        const float omask = clip01(wsum);
        const size_t RT3 = (size_t)NUM_R * 3;
        #pragma unroll
        for (int c = 0; c < 3; c++) {
            float medium = (1.0f - omask) * veilv[c];  // veiling at s=0
            float bs_ray = obs[c] + medium;
            out[0 * RT3 + (size_t)r * 3 + c] = clip01(dir[c] + bs_ray);  // rgb
            out[1 * RT3 + (size_t)r * 3 + c] = clip01(rest[c]);          // restored
            out[2 * RT3 + (size_t)r * 3 + c] = clip01(dir[c]);           // direct
            out[3 * RT3 + (size_t)r * 3 + c] = clip01(bs_ray);           // backscatter
        }
    }
}

extern "C" void kernel_launch(void* const* d_in, const int* in_sizes, int n_in,
                              void* d_out, int out_size) {
    const float* densities     = (const float*)d_in[0];
    const float* rgbs          = (const float*)d_in[1];
    const float* veiling       = (const float*)d_in[2];
    const float* direct_coeffs = (const float*)d_in[3];
    const float* backsc_coeffs = (const float*)d_in[4];
    const float* deltas        = (const float*)d_in[5];
    float* out = (float*)d_out;

    // 4 warps (4 rays) per 128-thread block -> 16384 blocks, exact cover.
    const int threads = 128;
    const int blocks  = (NUM_R * 32) / threads;
    uwnerf_render_kernel<<<blocks, threads>>>(
        densities, rgbs, veiling, direct_coeffs, backsc_coeffs, deltas, out);
}